// round 5
// baseline (speedup 1.0000x reference)
#include <cuda_runtime.h>
#include <cuda_bf16.h>

// SSIM preservation loss: 1 - mean(ssim_map(clean, adversarial))
// Inputs: clean [32,3,512,512] f32, adversarial [32,3,512,512] f32 -> scalar f32.
// Separable 11x11 Gaussian conv; vertical pass in per-thread packed-f32x2
// register rings, horizontal pass via smem with aligned LDS.64 + cross-packs,
// all heavy math in fma.rn.f32x2 (FFMA2 — 2x fma-pipe throughput vs scalar).
// Finalize fused via atomic ticket (deterministic, graph-replay safe).

#define IMG_W 512
#define IMG_H 512
#define ROWS_PER_BLOCK 32
#define STRIPS (IMG_H / ROWS_PER_BLOCK)   // 16
#define NPLANES 96                        // 32 batch * 3 channels
#define NBLOCKS (NPLANES * STRIPS)        // 1536
#define NTHREADS 256
#define TOTAL_PIX 25165824.0              // 32*3*512*512

// 1D Gaussian weights, sigma=1.5, normalized.
#define KW0 0.00102838f
#define KW1 0.00759876f
#define KW2 0.03600077f
#define KW3 0.10936070f
#define KW4 0.21300560f
#define KW5 0.26601170f

typedef unsigned long long u64;

__device__ double g_partials[NBLOCKS];
__device__ unsigned int g_ticket = 0;

// ---------- packed f32x2 primitives ----------
__device__ __forceinline__ u64 pack2(float lo, float hi) {
    u64 r; asm("mov.b64 %0, {%1, %2};" : "=l"(r) : "f"(lo), "f"(hi)); return r;
}
__device__ __forceinline__ void unpack2(u64 v, float& lo, float& hi) {
    asm("mov.b64 {%0, %1}, %2;" : "=f"(lo), "=f"(hi) : "l"(v));
}
__device__ __forceinline__ u64 fma2(u64 a, u64 b, u64 c) {
    u64 d; asm("fma.rn.f32x2 %0, %1, %2, %3;" : "=l"(d) : "l"(a), "l"(b), "l"(c)); return d;
}
__device__ __forceinline__ u64 mul2(u64 a, u64 b) {
    u64 d; asm("mul.rn.f32x2 %0, %1, %2;" : "=l"(d) : "l"(a), "l"(b)); return d;
}
__device__ __forceinline__ u64 add2(u64 a, u64 b) {
    u64 d; asm("add.rn.f32x2 %0, %1, %2;" : "=l"(d) : "l"(a), "l"(b)); return d;
}
// (a.hi, b.lo)
__device__ __forceinline__ u64 cross2(u64 a, u64 b) {
    u64 r;
    asm("{\n\t"
        ".reg .f32 alo, ahi, blo, bhi;\n\t"
        "mov.b64 {alo, ahi}, %1;\n\t"
        "mov.b64 {blo, bhi}, %2;\n\t"
        "mov.b64 %0, {ahi, blo};\n\t"
        "}" : "=l"(r) : "l"(a), "l"(b));
    return r;
}
__device__ __forceinline__ float frcp(float x) {
    float r; asm("rcp.approx.f32 %0, %1;" : "=f"(r) : "f"(x)); return r;
}

__global__ void __launch_bounds__(NTHREADS)
ssim_main(const float* __restrict__ X, const float* __restrict__ Y,
          float* __restrict__ out) {
    const int b     = blockIdx.x;
    const int plane = b >> 4;        // / STRIPS
    const int strip = b & 15;        // % STRIPS
    const int r0    = strip * ROWS_PER_BLOCK;
    const int t     = threadIdx.x;
    const int c0    = t * 2;

    const float* __restrict__ px = X + (size_t)plane * (IMG_H * IMG_W);
    const float* __restrict__ py = Y + (size_t)plane * (IMG_H * IMG_W);

    // Packed weight / constant registers
    const u64 WV0 = pack2(KW0, KW0);
    const u64 WV1 = pack2(KW1, KW1);
    const u64 WV2 = pack2(KW2, KW2);
    const u64 WV3 = pack2(KW3, KW3);
    const u64 WV4 = pack2(KW4, KW4);
    const u64 WV5 = pack2(KW5, KW5);
    const u64 NEG1v = pack2(-1.0f, -1.0f);
    const u64 TWOv  = pack2(2.0f, 2.0f);
    const u64 C1v   = pack2(1.0e-4f, 1.0e-4f);
    const u64 C2v   = pack2(9.0e-4f, 9.0e-4f);

    // Horizontal exchange buffers: index = 8 + col, col in [-5, 516]; pads zeroed.
    __shared__ float vbuf[2][5][528];
    __shared__ float warpsum[8];
    __shared__ bool  is_last;
    __shared__ double sd[NTHREADS];

    if (t < 5) {
        #pragma unroll
        for (int bb = 0; bb < 2; bb++) {
            #pragma unroll
            for (int i = 0; i < 8; i++) {
                vbuf[bb][t][i] = 0.0f;
                vbuf[bb][t][520 + i] = 0.0f;
            }
        }
    }

    // Register ring windows: 11 rows x (2 cols packed) per channel.
    u64 rx[11], ry[11], rxx[11], ryy[11], rxy[11];

    // Prime slots 0..9 with input rows r0-5 .. r0+4 (zero outside image).
    #pragma unroll
    for (int k = 0; k < 10; k++) {
        int ir = r0 - 5 + k;
        u64 vx = 0ull, vy = 0ull;
        if ((unsigned)ir < (unsigned)IMG_H) {
            vx = *(const u64*)(px + ir * IMG_W + c0);
            vy = *(const u64*)(py + ir * IMG_W + c0);
        }
        rx[k]  = vx;
        ry[k]  = vy;
        rxx[k] = mul2(vx, vx);
        ryy[k] = mul2(vy, vy);
        rxy[k] = mul2(vx, vy);
    }

    // Preload current row r0+5.
    u64 curx = 0ull, cury = 0ull;
    {
        int ir = r0 + 5;
        if (ir < IMG_H) {
            curx = *(const u64*)(px + ir * IMG_W + c0);
            cury = *(const u64*)(py + ir * IMG_W + c0);
        }
    }

    u64 accv = 0ull;   // packed (0.0f, 0.0f)

    for (int rr = 0; rr < ROWS_PER_BLOCK; rr += 11) {
        #pragma unroll
        for (int u = 0; u < 11; u++) {
            const int r = rr + u;
            if (r < ROWS_PER_BLOCK) {
                // ---- prefetch next input row ----
                u64 nx = 0ull, ny = 0ull;
                {
                    int irn = r0 + r + 6;
                    if (irn < IMG_H) {
                        nx = *(const u64*)(px + irn * IMG_W + c0);
                        ny = *(const u64*)(py + irn * IMG_W + c0);
                    }
                }

                // ---- push current row into ring slot (u+10)%11 ----
                {
                    const int s = (u + 10) % 11;
                    rx[s]  = curx;
                    ry[s]  = cury;
                    rxx[s] = mul2(curx, curx);
                    ryy[s] = mul2(cury, cury);
                    rxy[s] = mul2(curx, cury);
                }

                // ---- vertical 11-tap conv (packed) ----
                u64 m1, m2, e11, e22, e12;
                {
                    const int s0 = u % 11;
                    m1  = mul2(WV0, rx[s0]);
                    m2  = mul2(WV0, ry[s0]);
                    e11 = mul2(WV0, rxx[s0]);
                    e22 = mul2(WV0, ryy[s0]);
                    e12 = mul2(WV0, rxy[s0]);
                }
                #pragma unroll
                for (int tt = 1; tt < 11; tt++) {
                    const int sl = (u + tt) % 11;
                    const u64 w = (tt == 1 || tt == 9) ? WV1 :
                                  (tt == 2 || tt == 8) ? WV2 :
                                  (tt == 3 || tt == 7) ? WV3 :
                                  (tt == 4 || tt == 6) ? WV4 :
                                  (tt == 5)            ? WV5 : WV0;
                    m1  = fma2(w, rx[sl],  m1);
                    m2  = fma2(w, ry[sl],  m2);
                    e11 = fma2(w, rxx[sl], e11);
                    e22 = fma2(w, ryy[sl], e22);
                    e12 = fma2(w, rxy[sl], e12);
                }

                // ---- exchange via smem (double-buffered, 1 barrier/row) ----
                const int buf = r & 1;
                *(u64*)(&vbuf[buf][0][8 + c0]) = m1;
                *(u64*)(&vbuf[buf][1][8 + c0]) = m2;
                *(u64*)(&vbuf[buf][2][8 + c0]) = e11;
                *(u64*)(&vbuf[buf][3][8 + c0]) = e22;
                *(u64*)(&vbuf[buf][4][8 + c0]) = e12;
                __syncthreads();

                // ---- horizontal 11-tap conv (packed), 2 px per thread ----
                u64 hr2[5];
                u64 own[5] = {m1, m2, e11, e22, e12};
                #pragma unroll
                for (int q = 0; q < 5; q++) {
                    const float* vb = &vbuf[buf][q][8 + c0];
                    u64 Am3 = *(const u64*)(vb - 6);   // (v[-6], v[-5])
                    u64 Am2 = *(const u64*)(vb - 4);   // (v[-4], v[-3])
                    u64 Am1 = *(const u64*)(vb - 2);   // (v[-2], v[-1])
                    u64 A0  = own[q];                  // (v[0],  v[1])
                    u64 A1  = *(const u64*)(vb + 2);   // (v[2],  v[3])
                    u64 A2  = *(const u64*)(vb + 4);   // (v[4],  v[5])
                    u64 A3  = *(const u64*)(vb + 6);   // (v[6],  v[7])

                    u64 a = mul2(WV0, cross2(Am3, Am2));     // j=0
                    a = fma2(WV1, Am2, a);                   // j=1
                    a = fma2(WV2, cross2(Am2, Am1), a);      // j=2
                    a = fma2(WV3, Am1, a);                   // j=3
                    a = fma2(WV4, cross2(Am1, A0), a);       // j=4
                    a = fma2(WV5, A0, a);                    // j=5
                    a = fma2(WV4, cross2(A0, A1), a);        // j=6
                    a = fma2(WV3, A1, a);                    // j=7
                    a = fma2(WV2, cross2(A1, A2), a);        // j=8
                    a = fma2(WV1, A2, a);                    // j=9
                    a = fma2(WV0, cross2(A2, A3), a);        // j=10
                    hr2[q] = a;
                }

                // ---- SSIM per pixel pair (packed) ----
                {
                    u64 mu1 = hr2[0], mu2 = hr2[1];
                    u64 ex2 = hr2[2], ey2 = hr2[3], exy = hr2[4];
                    u64 mu1s = mul2(mu1, mu1);
                    u64 mu2s = mul2(mu2, mu2);
                    u64 mu12 = mul2(mu1, mu2);
                    u64 s1   = fma2(mu1s, NEG1v, ex2);
                    u64 s2   = fma2(mu2s, NEG1v, ey2);
                    u64 s12  = fma2(mu12, NEG1v, exy);
                    u64 num1 = fma2(TWOv, mu12, C1v);
                    u64 num2 = fma2(TWOv, s12, C2v);
                    u64 den1 = add2(add2(mu1s, mu2s), C1v);
                    u64 den2 = add2(add2(s1, s2), C2v);
                    u64 num  = mul2(num1, num2);
                    u64 den  = mul2(den1, den2);
                    float dlo, dhi;
                    unpack2(den, dlo, dhi);
                    u64 rcpv = pack2(frcp(dlo), frcp(dhi));
                    accv = fma2(num, rcpv, accv);
                }

                curx = nx;
                cury = ny;
            }
        }
    }

    float alo, ahi;
    unpack2(accv, alo, ahi);
    float acc = alo + ahi;

    // ---- deterministic block reduction ----
    #pragma unroll
    for (int off = 16; off > 0; off >>= 1)
        acc += __shfl_xor_sync(0xffffffffu, acc, off);
    if ((t & 31) == 0) warpsum[t >> 5] = acc;
    __syncthreads();
    if (t == 0) {
        float s = 0.0f;
        #pragma unroll
        for (int i = 0; i < 8; i++) s += warpsum[i];
        g_partials[b] = (double)s;
    }

    // ---- fused finalize: last block sums all partials (deterministic) ----
    __threadfence();
    if (t == 0) {
        unsigned int old = atomicAdd(&g_ticket, 1u);
        is_last = (old == NBLOCKS - 1);
    }
    __syncthreads();
    if (is_last) {
        double sm = 0.0;
        for (int i = t; i < NBLOCKS; i += NTHREADS) sm += g_partials[i];
        sd[t] = sm;
        __syncthreads();
        #pragma unroll
        for (int off = NTHREADS / 2; off > 0; off >>= 1) {
            if (t < off) sd[t] += sd[t + off];
            __syncthreads();
        }
        if (t == 0) {
            out[0] = (float)(1.0 - sd[0] / TOTAL_PIX);
            g_ticket = 0;   // reset for next graph replay
        }
    }
}

extern "C" void kernel_launch(void* const* d_in, const int* in_sizes, int n_in,
                              void* d_out, int out_size) {
    const float* clean = (const float*)d_in[0];
    const float* adv   = (const float*)d_in[1];
    ssim_main<<<NBLOCKS, NTHREADS>>>(clean, adv, (float*)d_out);
}

// round 9
// speedup vs baseline: 1.6025x; 1.6025x over previous
#include <cuda_runtime.h>
#include <cuda_bf16.h>

// SSIM preservation loss: 1 - mean(ssim_map(clean, adversarial))
// 4-channel transform: convolve s=x+y, d=x-y, s^2, d^2 (SSIM recoverable from
// these alone). Separable 11x11 Gaussian. Vertical pass keeps only s,d register
// rings (squares computed on the fly) so the kernel fits 128 regs and runs
// 2 CTAs/SM without spilling. Horizontal pass via smem, packed f32x2 math.

#define IMG_W 512
#define IMG_H 512
#define ROWS_PER_BLOCK 32
#define STRIPS (IMG_H / ROWS_PER_BLOCK)   // 16
#define NPLANES 96                        // 32 batch * 3 channels
#define NBLOCKS (NPLANES * STRIPS)        // 1536
#define NTHREADS 256
#define TOTAL_PIX 25165824.0              // 32*3*512*512

// 1D Gaussian weights, sigma=1.5, normalized.
#define KW0 0.00102838f
#define KW1 0.00759876f
#define KW2 0.03600077f
#define KW3 0.10936070f
#define KW4 0.21300560f
#define KW5 0.26601170f

typedef unsigned long long u64;

__device__ double g_partials[NBLOCKS];
__device__ unsigned int g_ticket = 0;

// ---------- packed f32x2 primitives ----------
__device__ __forceinline__ u64 pack2(float lo, float hi) {
    u64 r; asm("mov.b64 %0, {%1, %2};" : "=l"(r) : "f"(lo), "f"(hi)); return r;
}
__device__ __forceinline__ void unpack2(u64 v, float& lo, float& hi) {
    asm("mov.b64 {%0, %1}, %2;" : "=f"(lo), "=f"(hi) : "l"(v));
}
__device__ __forceinline__ u64 fma2(u64 a, u64 b, u64 c) {
    u64 d; asm("fma.rn.f32x2 %0, %1, %2, %3;" : "=l"(d) : "l"(a), "l"(b), "l"(c)); return d;
}
__device__ __forceinline__ u64 mul2(u64 a, u64 b) {
    u64 d; asm("mul.rn.f32x2 %0, %1, %2;" : "=l"(d) : "l"(a), "l"(b)); return d;
}
__device__ __forceinline__ u64 add2(u64 a, u64 b) {
    u64 d; asm("add.rn.f32x2 %0, %1, %2;" : "=l"(d) : "l"(a), "l"(b)); return d;
}
// (a.hi, b.lo)
__device__ __forceinline__ u64 cross2(u64 a, u64 b) {
    u64 r;
    asm("{\n\t"
        ".reg .f32 alo, ahi, blo, bhi;\n\t"
        "mov.b64 {alo, ahi}, %1;\n\t"
        "mov.b64 {blo, bhi}, %2;\n\t"
        "mov.b64 %0, {ahi, blo};\n\t"
        "}" : "=l"(r) : "l"(a), "l"(b));
    return r;
}
__device__ __forceinline__ float frcp(float x) {
    float r; asm("rcp.approx.f32 %0, %1;" : "=f"(r) : "f"(x)); return r;
}

__global__ void __launch_bounds__(NTHREADS, 2)
ssim_main(const float* __restrict__ X, const float* __restrict__ Y,
          float* __restrict__ out) {
    const int b     = blockIdx.x;
    const int plane = b >> 4;        // / STRIPS
    const int strip = b & 15;        // % STRIPS
    const int r0    = strip * ROWS_PER_BLOCK;
    const int t     = threadIdx.x;
    const int c0    = t * 2;

    const float* __restrict__ px = X + (size_t)plane * (IMG_H * IMG_W);
    const float* __restrict__ py = Y + (size_t)plane * (IMG_H * IMG_W);

    // Packed weights/constants.
    const u64 WV0 = pack2(KW0, KW0);
    const u64 WV1 = pack2(KW1, KW1);
    const u64 WV2 = pack2(KW2, KW2);
    const u64 WV3 = pack2(KW3, KW3);
    const u64 WV4 = pack2(KW4, KW4);
    const u64 WV5 = pack2(KW5, KW5);
    const u64 NEG1v = pack2(-1.0f, -1.0f);
    const u64 HALFv = pack2(0.5f, 0.5f);
    const u64 C1v   = pack2(1.0e-4f, 1.0e-4f);
    const u64 C2v   = pack2(9.0e-4f, 9.0e-4f);

    // Horizontal exchange buffers: index = 8 + col, col in [-5, 516]; pads zeroed.
    __shared__ float vbuf[2][4][528];
    __shared__ float warpsum[8];
    __shared__ bool  is_last;
    __shared__ double sd[NTHREADS];

    if (t < 4) {
        #pragma unroll
        for (int bb = 0; bb < 2; bb++) {
            #pragma unroll
            for (int i = 0; i < 8; i++) {
                vbuf[bb][t][i] = 0.0f;
                vbuf[bb][t][520 + i] = 0.0f;
            }
        }
    }

    // Register rings: 11 rows x (2 cols packed), channels s = x+y and d = x-y.
    // Squares are recomputed on the fly in the vertical pass (saves 44 regs).
    u64 rs[11], rd[11];

    // Prime slots 0..9 with input rows r0-5 .. r0+4 (zero outside image).
    #pragma unroll
    for (int k = 0; k < 10; k++) {
        int ir = r0 - 5 + k;
        u64 vx = 0ull, vy = 0ull;
        if ((unsigned)ir < (unsigned)IMG_H) {
            vx = *(const u64*)(px + ir * IMG_W + c0);
            vy = *(const u64*)(py + ir * IMG_W + c0);
        }
        rs[k] = add2(vx, vy);
        rd[k] = fma2(vy, NEG1v, vx);
    }

    // Preload current row r0+5.
    u64 curx = 0ull, cury = 0ull;
    {
        int ir = r0 + 5;
        if (ir < IMG_H) {
            curx = *(const u64*)(px + ir * IMG_W + c0);
            cury = *(const u64*)(py + ir * IMG_W + c0);
        }
    }

    u64 accv = 0ull;   // packed (0.0f, 0.0f)

    for (int rr = 0; rr < ROWS_PER_BLOCK; rr += 11) {
        #pragma unroll
        for (int u = 0; u < 11; u++) {
            const int r = rr + u;
            if (r < ROWS_PER_BLOCK) {
                // ---- prefetch next input row ----
                u64 nx = 0ull, ny = 0ull;
                {
                    int irn = r0 + r + 6;
                    if (irn < IMG_H) {
                        nx = *(const u64*)(px + irn * IMG_W + c0);
                        ny = *(const u64*)(py + irn * IMG_W + c0);
                    }
                }

                // ---- push current row into ring slot (u+10)%11 ----
                {
                    const int sl = (u + 10) % 11;
                    rs[sl] = add2(curx, cury);
                    rd[sl] = fma2(cury, NEG1v, curx);
                }

                // ---- vertical 11-tap conv (packed); squares on the fly ----
                u64 ms, md, es, ed;
                {
                    const int s0 = u % 11;
                    u64 sv = rs[s0], dv = rd[s0];
                    ms = mul2(WV0, sv);
                    md = mul2(WV0, dv);
                    es = mul2(WV0, mul2(sv, sv));
                    ed = mul2(WV0, mul2(dv, dv));
                }
                #pragma unroll
                for (int tt = 1; tt < 11; tt++) {
                    const int sl = (u + tt) % 11;
                    const u64 w = (tt == 1 || tt == 9) ? WV1 :
                                  (tt == 2 || tt == 8) ? WV2 :
                                  (tt == 3 || tt == 7) ? WV3 :
                                  (tt == 4 || tt == 6) ? WV4 :
                                  (tt == 5)            ? WV5 : WV0;
                    u64 sv = rs[sl], dv = rd[sl];
                    ms = fma2(w, sv, ms);
                    md = fma2(w, dv, md);
                    es = fma2(w, mul2(sv, sv), es);
                    ed = fma2(w, mul2(dv, dv), ed);
                }

                // ---- exchange via smem (double-buffered, 1 barrier/row) ----
                const int buf = r & 1;
                *(u64*)(&vbuf[buf][0][8 + c0]) = ms;
                *(u64*)(&vbuf[buf][1][8 + c0]) = md;
                *(u64*)(&vbuf[buf][2][8 + c0]) = es;
                *(u64*)(&vbuf[buf][3][8 + c0]) = ed;
                __syncthreads();

                // ---- horizontal 11-tap conv (packed), 2 px per thread ----
                u64 hr2[4];
                u64 own[4] = {ms, md, es, ed};
                #pragma unroll
                for (int q = 0; q < 4; q++) {
                    const float* vb = &vbuf[buf][q][8 + c0];
                    u64 Am3 = *(const u64*)(vb - 6);
                    u64 Am2 = *(const u64*)(vb - 4);
                    u64 Am1 = *(const u64*)(vb - 2);
                    u64 A0  = own[q];
                    u64 A1  = *(const u64*)(vb + 2);
                    u64 A2  = *(const u64*)(vb + 4);
                    u64 A3  = *(const u64*)(vb + 6);

                    u64 a = mul2(WV0, cross2(Am3, Am2));
                    a = fma2(WV1, Am2, a);
                    a = fma2(WV2, cross2(Am2, Am1), a);
                    a = fma2(WV3, Am1, a);
                    a = fma2(WV4, cross2(Am1, A0), a);
                    a = fma2(WV5, A0, a);
                    a = fma2(WV4, cross2(A0, A1), a);
                    a = fma2(WV3, A1, a);
                    a = fma2(WV2, cross2(A1, A2), a);
                    a = fma2(WV1, A2, a);
                    a = fma2(WV0, cross2(A2, A3), a);
                    hr2[q] = a;
                }

                // ---- SSIM from 4-channel transform (packed) ----
                {
                    u64 MS = hr2[0], MD = hr2[1], ES = hr2[2], ED = hr2[3];
                    u64 A  = mul2(MS, MS);
                    u64 B  = mul2(MD, MD);
                    u64 hA = mul2(HALFv, A);
                    u64 hB = mul2(HALFv, B);
                    u64 P  = add2(hA, hB);                 // mu1^2 + mu2^2
                    u64 Q  = fma2(hB, NEG1v, hA);          // 2*mu1*mu2
                    u64 hES = mul2(HALFv, ES);
                    u64 hED = mul2(HALFv, ED);
                    u64 Rv = fma2(P, NEG1v, add2(hES, hED));            // sig1+sig2
                    u64 Tv = fma2(Q, NEG1v, fma2(hED, NEG1v, hES));     // 2*sig12
                    u64 num = mul2(add2(Q, C1v), add2(Tv, C2v));
                    u64 den = mul2(add2(P, C1v), add2(Rv, C2v));
                    float dlo, dhi;
                    unpack2(den, dlo, dhi);
                    u64 rcpv = pack2(frcp(dlo), frcp(dhi));
                    accv = fma2(num, rcpv, accv);
                }

                curx = nx;
                cury = ny;
            }
        }
    }

    float alo, ahi;
    unpack2(accv, alo, ahi);
    float acc = alo + ahi;

    // ---- deterministic block reduction ----
    #pragma unroll
    for (int off = 16; off > 0; off >>= 1)
        acc += __shfl_xor_sync(0xffffffffu, acc, off);
    if ((t & 31) == 0) warpsum[t >> 5] = acc;
    __syncthreads();
    if (t == 0) {
        float s = 0.0f;
        #pragma unroll
        for (int i = 0; i < 8; i++) s += warpsum[i];
        g_partials[b] = (double)s;
    }

    // ---- fused finalize: last block sums all partials (deterministic) ----
    __threadfence();
    if (t == 0) {
        unsigned int old = atomicAdd(&g_ticket, 1u);
        is_last = (old == NBLOCKS - 1);
    }
    __syncthreads();
    if (is_last) {
        double sm = 0.0;
        for (int i = t; i < NBLOCKS; i += NTHREADS) sm += g_partials[i];
        sd[t] = sm;
        __syncthreads();
        #pragma unroll
        for (int off = NTHREADS / 2; off > 0; off >>= 1) {
            if (t < off) sd[t] += sd[t + off];
            __syncthreads();
        }
        if (t == 0) {
            out[0] = (float)(1.0 - sd[0] / TOTAL_PIX);
            g_ticket = 0;   // reset for next graph replay
        }
    }
}

extern "C" void kernel_launch(void* const* d_in, const int* in_sizes, int n_in,
                              void* d_out, int out_size) {
    const float* clean = (const float*)d_in[0];
    const float* adv   = (const float*)d_in[1];
    ssim_main<<<NBLOCKS, NTHREADS>>>(clean, adv, (float*)d_out);
}

// round 10
// speedup vs baseline: 1.7768x; 1.1088x over previous
#include <cuda_runtime.h>
#include <cuda_bf16.h>

// SSIM preservation loss: 1 - mean(ssim_map(clean, adversarial))
// 4-channel transform: convolve s=x+y, d=x-y, s^2, d^2 (SSIM recoverable from
// these alone). Separable 11x11 Gaussian. Vertical pass keeps only s,d register
// rings (squares computed on the fly) so the kernel fits 128 regs and runs
// 2 CTAs/SM without spilling. Horizontal pass via smem, packed f32x2 math.
// R10: ROWS_PER_BLOCK=16 — finer strips cut wave-quantization tail 13.5%->5.6%.

#define IMG_W 512
#define IMG_H 512
#define ROWS_PER_BLOCK 16
#define STRIPS (IMG_H / ROWS_PER_BLOCK)   // 32
#define NPLANES 96                        // 32 batch * 3 channels
#define NBLOCKS (NPLANES * STRIPS)        // 3072
#define NTHREADS 256
#define TOTAL_PIX 25165824.0              // 32*3*512*512

// 1D Gaussian weights, sigma=1.5, normalized.
#define KW0 0.00102838f
#define KW1 0.00759876f
#define KW2 0.03600077f
#define KW3 0.10936070f
#define KW4 0.21300560f
#define KW5 0.26601170f

typedef unsigned long long u64;

__device__ double g_partials[NBLOCKS];
__device__ unsigned int g_ticket = 0;

// ---------- packed f32x2 primitives ----------
__device__ __forceinline__ u64 pack2(float lo, float hi) {
    u64 r; asm("mov.b64 %0, {%1, %2};" : "=l"(r) : "f"(lo), "f"(hi)); return r;
}
__device__ __forceinline__ void unpack2(u64 v, float& lo, float& hi) {
    asm("mov.b64 {%0, %1}, %2;" : "=f"(lo), "=f"(hi) : "l"(v));
}
__device__ __forceinline__ u64 fma2(u64 a, u64 b, u64 c) {
    u64 d; asm("fma.rn.f32x2 %0, %1, %2, %3;" : "=l"(d) : "l"(a), "l"(b), "l"(c)); return d;
}
__device__ __forceinline__ u64 mul2(u64 a, u64 b) {
    u64 d; asm("mul.rn.f32x2 %0, %1, %2;" : "=l"(d) : "l"(a), "l"(b)); return d;
}
__device__ __forceinline__ u64 add2(u64 a, u64 b) {
    u64 d; asm("add.rn.f32x2 %0, %1, %2;" : "=l"(d) : "l"(a), "l"(b)); return d;
}
// (a.hi, b.lo)
__device__ __forceinline__ u64 cross2(u64 a, u64 b) {
    u64 r;
    asm("{\n\t"
        ".reg .f32 alo, ahi, blo, bhi;\n\t"
        "mov.b64 {alo, ahi}, %1;\n\t"
        "mov.b64 {blo, bhi}, %2;\n\t"
        "mov.b64 %0, {ahi, blo};\n\t"
        "}" : "=l"(r) : "l"(a), "l"(b));
    return r;
}
__device__ __forceinline__ float frcp(float x) {
    float r; asm("rcp.approx.f32 %0, %1;" : "=f"(r) : "f"(x)); return r;
}

__global__ void __launch_bounds__(NTHREADS, 2)
ssim_main(const float* __restrict__ X, const float* __restrict__ Y,
          float* __restrict__ out) {
    const int b     = blockIdx.x;
    const int plane = b >> 5;        // / STRIPS
    const int strip = b & 31;        // % STRIPS
    const int r0    = strip * ROWS_PER_BLOCK;
    const int t     = threadIdx.x;
    const int c0    = t * 2;

    const float* __restrict__ px = X + (size_t)plane * (IMG_H * IMG_W);
    const float* __restrict__ py = Y + (size_t)plane * (IMG_H * IMG_W);

    // Packed weights/constants.
    const u64 WV0 = pack2(KW0, KW0);
    const u64 WV1 = pack2(KW1, KW1);
    const u64 WV2 = pack2(KW2, KW2);
    const u64 WV3 = pack2(KW3, KW3);
    const u64 WV4 = pack2(KW4, KW4);
    const u64 WV5 = pack2(KW5, KW5);
    const u64 NEG1v = pack2(-1.0f, -1.0f);
    const u64 HALFv = pack2(0.5f, 0.5f);
    const u64 C1v   = pack2(1.0e-4f, 1.0e-4f);
    const u64 C2v   = pack2(9.0e-4f, 9.0e-4f);

    // Horizontal exchange buffers: index = 8 + col, col in [-5, 516]; pads zeroed.
    __shared__ float vbuf[2][4][528];
    __shared__ float warpsum[8];
    __shared__ bool  is_last;
    __shared__ double sd[NTHREADS];

    if (t < 4) {
        #pragma unroll
        for (int bb = 0; bb < 2; bb++) {
            #pragma unroll
            for (int i = 0; i < 8; i++) {
                vbuf[bb][t][i] = 0.0f;
                vbuf[bb][t][520 + i] = 0.0f;
            }
        }
    }

    // Register rings: 11 rows x (2 cols packed), channels s = x+y and d = x-y.
    // Squares are recomputed on the fly in the vertical pass (saves 44 regs).
    u64 rs[11], rd[11];

    // Prime slots 0..9 with input rows r0-5 .. r0+4 (zero outside image).
    #pragma unroll
    for (int k = 0; k < 10; k++) {
        int ir = r0 - 5 + k;
        u64 vx = 0ull, vy = 0ull;
        if ((unsigned)ir < (unsigned)IMG_H) {
            vx = *(const u64*)(px + ir * IMG_W + c0);
            vy = *(const u64*)(py + ir * IMG_W + c0);
        }
        rs[k] = add2(vx, vy);
        rd[k] = fma2(vy, NEG1v, vx);
    }

    // Preload current row r0+5.
    u64 curx = 0ull, cury = 0ull;
    {
        int ir = r0 + 5;
        if (ir < IMG_H) {
            curx = *(const u64*)(px + ir * IMG_W + c0);
            cury = *(const u64*)(py + ir * IMG_W + c0);
        }
    }

    u64 accv = 0ull;   // packed (0.0f, 0.0f)

    #pragma unroll
    for (int rr = 0; rr < ROWS_PER_BLOCK; rr += 11) {
        #pragma unroll
        for (int u = 0; u < 11; u++) {
            const int r = rr + u;
            if (r < ROWS_PER_BLOCK) {
                // ---- prefetch next input row ----
                u64 nx = 0ull, ny = 0ull;
                {
                    int irn = r0 + r + 6;
                    if (irn < IMG_H) {
                        nx = *(const u64*)(px + irn * IMG_W + c0);
                        ny = *(const u64*)(py + irn * IMG_W + c0);
                    }
                }

                // ---- push current row into ring slot (u+10)%11 ----
                {
                    const int sl = (u + 10) % 11;
                    rs[sl] = add2(curx, cury);
                    rd[sl] = fma2(cury, NEG1v, curx);
                }

                // ---- vertical 11-tap conv (packed); squares on the fly ----
                u64 ms, md, es, ed;
                {
                    const int s0 = u % 11;
                    u64 sv = rs[s0], dv = rd[s0];
                    ms = mul2(WV0, sv);
                    md = mul2(WV0, dv);
                    es = mul2(WV0, mul2(sv, sv));
                    ed = mul2(WV0, mul2(dv, dv));
                }
                #pragma unroll
                for (int tt = 1; tt < 11; tt++) {
                    const int sl = (u + tt) % 11;
                    const u64 w = (tt == 1 || tt == 9) ? WV1 :
                                  (tt == 2 || tt == 8) ? WV2 :
                                  (tt == 3 || tt == 7) ? WV3 :
                                  (tt == 4 || tt == 6) ? WV4 :
                                  (tt == 5)            ? WV5 : WV0;
                    u64 sv = rs[sl], dv = rd[sl];
                    ms = fma2(w, sv, ms);
                    md = fma2(w, dv, md);
                    es = fma2(w, mul2(sv, sv), es);
                    ed = fma2(w, mul2(dv, dv), ed);
                }

                // ---- exchange via smem (double-buffered, 1 barrier/row) ----
                const int buf = r & 1;
                *(u64*)(&vbuf[buf][0][8 + c0]) = ms;
                *(u64*)(&vbuf[buf][1][8 + c0]) = md;
                *(u64*)(&vbuf[buf][2][8 + c0]) = es;
                *(u64*)(&vbuf[buf][3][8 + c0]) = ed;
                __syncthreads();

                // ---- horizontal 11-tap conv (packed), 2 px per thread ----
                u64 hr2[4];
                u64 own[4] = {ms, md, es, ed};
                #pragma unroll
                for (int q = 0; q < 4; q++) {
                    const float* vb = &vbuf[buf][q][8 + c0];
                    u64 Am3 = *(const u64*)(vb - 6);
                    u64 Am2 = *(const u64*)(vb - 4);
                    u64 Am1 = *(const u64*)(vb - 2);
                    u64 A0  = own[q];
                    u64 A1  = *(const u64*)(vb + 2);
                    u64 A2  = *(const u64*)(vb + 4);
                    u64 A3  = *(const u64*)(vb + 6);

                    u64 a = mul2(WV0, cross2(Am3, Am2));
                    a = fma2(WV1, Am2, a);
                    a = fma2(WV2, cross2(Am2, Am1), a);
                    a = fma2(WV3, Am1, a);
                    a = fma2(WV4, cross2(Am1, A0), a);
                    a = fma2(WV5, A0, a);
                    a = fma2(WV4, cross2(A0, A1), a);
                    a = fma2(WV3, A1, a);
                    a = fma2(WV2, cross2(A1, A2), a);
                    a = fma2(WV1, A2, a);
                    a = fma2(WV0, cross2(A2, A3), a);
                    hr2[q] = a;
                }

                // ---- SSIM from 4-channel transform (packed) ----
                {
                    u64 MS = hr2[0], MD = hr2[1], ES = hr2[2], ED = hr2[3];
                    u64 A  = mul2(MS, MS);
                    u64 B  = mul2(MD, MD);
                    u64 hA = mul2(HALFv, A);
                    u64 hB = mul2(HALFv, B);
                    u64 P  = add2(hA, hB);                 // mu1^2 + mu2^2
                    u64 Q  = fma2(hB, NEG1v, hA);          // 2*mu1*mu2
                    u64 hES = mul2(HALFv, ES);
                    u64 hED = mul2(HALFv, ED);
                    u64 Rv = fma2(P, NEG1v, add2(hES, hED));            // sig1+sig2
                    u64 Tv = fma2(Q, NEG1v, fma2(hED, NEG1v, hES));     // 2*sig12
                    u64 num = mul2(add2(Q, C1v), add2(Tv, C2v));
                    u64 den = mul2(add2(P, C1v), add2(Rv, C2v));
                    float dlo, dhi;
                    unpack2(den, dlo, dhi);
                    u64 rcpv = pack2(frcp(dlo), frcp(dhi));
                    accv = fma2(num, rcpv, accv);
                }

                curx = nx;
                cury = ny;
            }
        }
    }

    float alo, ahi;
    unpack2(accv, alo, ahi);
    float acc = alo + ahi;

    // ---- deterministic block reduction ----
    #pragma unroll
    for (int off = 16; off > 0; off >>= 1)
        acc += __shfl_xor_sync(0xffffffffu, acc, off);
    if ((t & 31) == 0) warpsum[t >> 5] = acc;
    __syncthreads();
    if (t == 0) {
        float s = 0.0f;
        #pragma unroll
        for (int i = 0; i < 8; i++) s += warpsum[i];
        g_partials[b] = (double)s;
    }

    // ---- fused finalize: last block sums all partials (deterministic) ----
    __threadfence();
    if (t == 0) {
        unsigned int old = atomicAdd(&g_ticket, 1u);
        is_last = (old == NBLOCKS - 1);
    }
    __syncthreads();
    if (is_last) {
        double sm = 0.0;
        for (int i = t; i < NBLOCKS; i += NTHREADS) sm += g_partials[i];
        sd[t] = sm;
        __syncthreads();
        #pragma unroll
        for (int off = NTHREADS / 2; off > 0; off >>= 1) {
            if (t < off) sd[t] += sd[t + off];
            __syncthreads();
        }
        if (t == 0) {
            out[0] = (float)(1.0 - sd[0] / TOTAL_PIX);
            g_ticket = 0;   // reset for next graph replay
        }
    }
}

extern "C" void kernel_launch(void* const* d_in, const int* in_sizes, int n_in,
                              void* d_out, int out_size) {
    const float* clean = (const float*)d_in[0];
    const float* adv   = (const float*)d_in[1];
    ssim_main<<<NBLOCKS, NTHREADS>>>(clean, adv, (float*)d_out);
}

// round 13
// speedup vs baseline: 1.8590x; 1.0463x over previous
#include <cuda_runtime.h>
#include <cuda_bf16.h>

// SSIM preservation loss: 1 - mean(ssim_map(clean, adversarial))
// 4-channel transform: convolve s=x+y, d=x-y, s^2, d^2. Separable 11x11
// Gaussian. Vertical pass: packed-f32x2 register rings (squares on the fly).
// Horizontal pass: scalar FFMA with immediate weights (FFMA-imm rt=1, no
// cross-pack movs), operands read as halves of LDS.64 halo loads.
// R11: 2 rows per barrier via 4 smem buffers (8 barriers/block).

#define IMG_W 512
#define IMG_H 512
#define ROWS_PER_BLOCK 16
#define STRIPS (IMG_H / ROWS_PER_BLOCK)   // 32
#define NPLANES 96                        // 32 batch * 3 channels
#define NBLOCKS (NPLANES * STRIPS)        // 3072
#define NTHREADS 256
#define TOTAL_PIX 25165824.0              // 32*3*512*512

// 1D Gaussian weights, sigma=1.5, normalized.
#define KW0 0.00102838f
#define KW1 0.00759876f
#define KW2 0.03600077f
#define KW3 0.10936070f
#define KW4 0.21300560f
#define KW5 0.26601170f

typedef unsigned long long u64;

__device__ double g_partials[NBLOCKS];
__device__ unsigned int g_ticket = 0;

// ---------- packed f32x2 primitives ----------
__device__ __forceinline__ u64 pack2(float lo, float hi) {
    u64 r; asm("mov.b64 %0, {%1, %2};" : "=l"(r) : "f"(lo), "f"(hi)); return r;
}
__device__ __forceinline__ void unpack2(u64 v, float& lo, float& hi) {
    asm("mov.b64 {%0, %1}, %2;" : "=f"(lo), "=f"(hi) : "l"(v));
}
__device__ __forceinline__ u64 fma2(u64 a, u64 b, u64 c) {
    u64 d; asm("fma.rn.f32x2 %0, %1, %2, %3;" : "=l"(d) : "l"(a), "l"(b), "l"(c)); return d;
}
__device__ __forceinline__ u64 mul2(u64 a, u64 b) {
    u64 d; asm("mul.rn.f32x2 %0, %1, %2;" : "=l"(d) : "l"(a), "l"(b)); return d;
}
__device__ __forceinline__ u64 add2(u64 a, u64 b) {
    u64 d; asm("add.rn.f32x2 %0, %1, %2;" : "=l"(d) : "l"(a), "l"(b)); return d;
}
__device__ __forceinline__ float frcp(float x) {
    float r; asm("rcp.approx.f32 %0, %1;" : "=f"(r) : "f"(x)); return r;
}

__global__ void __launch_bounds__(NTHREADS, 2)
ssim_main(const float* __restrict__ X, const float* __restrict__ Y,
          float* __restrict__ out) {
    const int b     = blockIdx.x;
    const int plane = b >> 5;        // / STRIPS
    const int strip = b & 31;        // % STRIPS
    const int r0    = strip * ROWS_PER_BLOCK;
    const int t     = threadIdx.x;
    const int c0    = t * 2;

    const float* __restrict__ px = X + (size_t)plane * (IMG_H * IMG_W);
    const float* __restrict__ py = Y + (size_t)plane * (IMG_H * IMG_W);

    // Packed weights (vertical pass needs register weights for FFMA2).
    const u64 WV0 = pack2(KW0, KW0);
    const u64 WV1 = pack2(KW1, KW1);
    const u64 WV2 = pack2(KW2, KW2);
    const u64 WV3 = pack2(KW3, KW3);
    const u64 WV4 = pack2(KW4, KW4);
    const u64 WV5 = pack2(KW5, KW5);
    const u64 NEG1v = pack2(-1.0f, -1.0f);
    const u64 HALFv = pack2(0.5f, 0.5f);
    const u64 C1v   = pack2(1.0e-4f, 1.0e-4f);
    const u64 C2v   = pack2(9.0e-4f, 9.0e-4f);

    // 4 row buffers (2 row-pairs double-buffered): index = 8 + col.
    __shared__ float vbuf[4][4][528];
    __shared__ float warpsum[8];
    __shared__ bool  is_last;
    __shared__ double sd[NTHREADS];

    if (t < 4) {
        #pragma unroll
        for (int bb = 0; bb < 4; bb++) {
            #pragma unroll
            for (int i = 0; i < 8; i++) {
                vbuf[bb][t][i] = 0.0f;
                vbuf[bb][t][520 + i] = 0.0f;
            }
        }
    }

    // Register rings: 11 rows x (2 cols packed), channels s = x+y, d = x-y.
    u64 rs[11], rd[11];

    // Prime slots 0..9 with input rows r0-5 .. r0+4 (zero outside image).
    #pragma unroll
    for (int k = 0; k < 10; k++) {
        int ir = r0 - 5 + k;
        u64 vx = 0ull, vy = 0ull;
        if ((unsigned)ir < (unsigned)IMG_H) {
            vx = *(const u64*)(px + ir * IMG_W + c0);
            vy = *(const u64*)(py + ir * IMG_W + c0);
        }
        rs[k] = add2(vx, vy);
        rd[k] = fma2(vy, NEG1v, vx);
    }

    // Preload current row r0+5.
    u64 curx = 0ull, cury = 0ull;
    {
        int ir = r0 + 5;
        if (ir < IMG_H) {
            curx = *(const u64*)(px + ir * IMG_W + c0);
            cury = *(const u64*)(py + ir * IMG_W + c0);
        }
    }

    u64 accv = 0ull;   // packed (0.0f, 0.0f)

    #pragma unroll
    for (int rp = 0; rp < ROWS_PER_BLOCK / 2; rp++) {
        const int r  = 2 * rp;
        const int pb = rp & 1;           // buffer pair select: {0,1} or {2,3}

        // ---- prefetch the two rows consumed by this pair ----
        u64 nax = 0ull, nay = 0ull, nbx = 0ull, nby = 0ull;
        {
            int ira = r0 + r + 6;
            int irb = r0 + r + 7;
            if ((unsigned)ira < (unsigned)IMG_H) {
                nax = *(const u64*)(px + ira * IMG_W + c0);
                nay = *(const u64*)(py + ira * IMG_W + c0);
            }
            if ((unsigned)irb < (unsigned)IMG_H) {
                nbx = *(const u64*)(px + irb * IMG_W + c0);
                nby = *(const u64*)(py + irb * IMG_W + c0);
            }
        }

        // ---- vertical pass for the two rows of this pair ----
        #pragma unroll
        for (int sub = 0; sub < 2; sub++) {
            const int rr = r + sub;
            // push current row (r0+rr+5) into ring slot (rr+10)%11
            {
                const int sl = (rr + 10) % 11;
                rs[sl] = add2(curx, cury);
                rd[sl] = fma2(cury, NEG1v, curx);
            }
            // 11-tap vertical conv (packed, squares on the fly)
            u64 ms, md, es, ed;
            {
                const int s0 = rr % 11;
                u64 sv = rs[s0], dv = rd[s0];
                ms = mul2(WV0, sv);
                md = mul2(WV0, dv);
                es = mul2(WV0, mul2(sv, sv));
                ed = mul2(WV0, mul2(dv, dv));
            }
            #pragma unroll
            for (int tt = 1; tt < 11; tt++) {
                const int sl = (rr + tt) % 11;
                const u64 w = (tt == 1 || tt == 9) ? WV1 :
                              (tt == 2 || tt == 8) ? WV2 :
                              (tt == 3 || tt == 7) ? WV3 :
                              (tt == 4 || tt == 6) ? WV4 :
                              (tt == 5)            ? WV5 : WV0;
                u64 sv = rs[sl], dv = rd[sl];
                ms = fma2(w, sv, ms);
                md = fma2(w, dv, md);
                es = fma2(w, mul2(sv, sv), es);
                ed = fma2(w, mul2(dv, dv), ed);
            }
            const int buf = 2 * pb + sub;
            *(u64*)(&vbuf[buf][0][8 + c0]) = ms;
            *(u64*)(&vbuf[buf][1][8 + c0]) = md;
            *(u64*)(&vbuf[buf][2][8 + c0]) = es;
            *(u64*)(&vbuf[buf][3][8 + c0]) = ed;
            // advance current row
            curx = sub ? nbx : nax;
            cury = sub ? nby : nay;
        }

        __syncthreads();   // one barrier per 2 rows

        // ---- horizontal pass + SSIM for both rows (scalar FFMA-imm) ----
        #pragma unroll
        for (int sub = 0; sub < 2; sub++) {
            const int buf = 2 * pb + sub;
            u64 hr2[4];
            #pragma unroll
            for (int q = 0; q < 4; q++) {
                const float2* vb = (const float2*)(&vbuf[buf][q][8 + c0 - 6]);
                float2 f0 = vb[0];   // v[-6], v[-5]
                float2 f1 = vb[1];   // v[-4], v[-3]
                float2 f2 = vb[2];   // v[-2], v[-1]
                float2 f3 = vb[3];   // v[0],  v[1]
                float2 f4 = vb[4];   // v[2],  v[3]
                float2 f5 = vb[5];   // v[4],  v[5]
                float2 f6 = vb[6];   // v[6],  v[7]

                float p0 = KW0 * f0.y;
                p0 = fmaf(KW1, f1.x, p0);
                p0 = fmaf(KW2, f1.y, p0);
                p0 = fmaf(KW3, f2.x, p0);
                p0 = fmaf(KW4, f2.y, p0);
                p0 = fmaf(KW5, f3.x, p0);
                p0 = fmaf(KW4, f3.y, p0);
                p0 = fmaf(KW3, f4.x, p0);
                p0 = fmaf(KW2, f4.y, p0);
                p0 = fmaf(KW1, f5.x, p0);
                p0 = fmaf(KW0, f5.y, p0);

                float p1 = KW0 * f1.x;
                p1 = fmaf(KW1, f1.y, p1);
                p1 = fmaf(KW2, f2.x, p1);
                p1 = fmaf(KW3, f2.y, p1);
                p1 = fmaf(KW4, f3.x, p1);
                p1 = fmaf(KW5, f3.y, p1);
                p1 = fmaf(KW4, f4.x, p1);
                p1 = fmaf(KW3, f4.y, p1);
                p1 = fmaf(KW2, f5.x, p1);
                p1 = fmaf(KW1, f5.y, p1);
                p1 = fmaf(KW0, f6.x, p1);

                hr2[q] = pack2(p0, p1);
            }

            // ---- SSIM from 4-channel transform (packed) ----
            {
                u64 MS = hr2[0], MD = hr2[1], ES = hr2[2], ED = hr2[3];
                u64 A  = mul2(MS, MS);
                u64 B  = mul2(MD, MD);
                u64 hA = mul2(HALFv, A);
                u64 hB = mul2(HALFv, B);
                u64 P  = add2(hA, hB);                 // mu1^2 + mu2^2
                u64 Q  = fma2(hB, NEG1v, hA);          // 2*mu1*mu2
                u64 hES = mul2(HALFv, ES);
                u64 hED = mul2(HALFv, ED);
                u64 Rv = fma2(P, NEG1v, add2(hES, hED));            // sig1+sig2
                u64 Tv = fma2(Q, NEG1v, fma2(hED, NEG1v, hES));     // 2*sig12
                u64 num = mul2(add2(Q, C1v), add2(Tv, C2v));
                u64 den = mul2(add2(P, C1v), add2(Rv, C2v));
                float dlo, dhi;
                unpack2(den, dlo, dhi);
                u64 rcpv = pack2(frcp(dlo), frcp(dhi));
                accv = fma2(num, rcpv, accv);
            }
        }
    }

    float alo, ahi;
    unpack2(accv, alo, ahi);
    float acc = alo + ahi;

    // ---- deterministic block reduction ----
    #pragma unroll
    for (int off = 16; off > 0; off >>= 1)
        acc += __shfl_xor_sync(0xffffffffu, acc, off);
    if ((t & 31) == 0) warpsum[t >> 5] = acc;
    __syncthreads();
    if (t == 0) {
        float s = 0.0f;
        #pragma unroll
        for (int i = 0; i < 8; i++) s += warpsum[i];
        g_partials[b] = (double)s;
    }

    // ---- fused finalize: last block sums all partials (deterministic) ----
    __threadfence();
    if (t == 0) {
        unsigned int old = atomicAdd(&g_ticket, 1u);
        is_last = (old == NBLOCKS - 1);
    }
    __syncthreads();
    if (is_last) {
        double sm = 0.0;
        for (int i = t; i < NBLOCKS; i += NTHREADS) sm += g_partials[i];
        sd[t] = sm;
        __syncthreads();
        #pragma unroll
        for (int off = NTHREADS / 2; off > 0; off >>= 1) {
            if (t < off) sd[t] += sd[t + off];
            __syncthreads();
        }
        if (t == 0) {
            out[0] = (float)(1.0 - sd[0] / TOTAL_PIX);
            g_ticket = 0;   // reset for next graph replay
        }
    }
}

extern "C" void kernel_launch(void* const* d_in, const int* in_sizes, int n_in,
                              void* d_out, int out_size) {
    const float* clean = (const float*)d_in[0];
    const float* adv   = (const float*)d_in[1];
    ssim_main<<<NBLOCKS, NTHREADS>>>(clean, adv, (float*)d_out);
}